// round 1
// baseline (speedup 1.0000x reference)
#include <cuda_runtime.h>

// Reverse cummax along axis 1 of [B=16, H=128, W=128, C=256] float32.
// out[b,h,w,c] = max over h' >= h of in[b,h',w,c].
//
// Pure streaming problem: one thread owns one (b, w, c4) float4 column and
// walks H from the end, carrying a running max. Loads across the unrolled
// window are address-independent -> high MLP; stores stream out.

#define B 16
#define H 128
#define WC4 8192              // W*C/4 float4 per (b,h) slab = 128*256/4
#define HSTRIDE 8192          // stride (in float4) between consecutive h
#define NCOLS (B * WC4)       // 131072 columns

__global__ __launch_bounds__(256) void revcummax_kernel(
    const float4* __restrict__ in, float4* __restrict__ out) {
    int idx = blockIdx.x * blockDim.x + threadIdx.x;
    if (idx >= NCOLS) return;

    int b = idx >> 13;          // / WC4
    int inner = idx & (WC4 - 1);
    long long base = (long long)b * H * (long long)HSTRIDE + inner;

    const float4* p = in + base + (H - 1) * (long long)HSTRIDE;
    float4* q = out + base + (H - 1) * (long long)HSTRIDE;

    // h = H-1: copy through
    float4 m = __ldcs((const float4*)p);
    __stcs(q, m);

    // h = H-2 .. 0
#pragma unroll 8
    for (int h = H - 2; h >= 0; --h) {
        p -= HSTRIDE;
        q -= HSTRIDE;
        float4 v = __ldcs((const float4*)p);
        m.x = fmaxf(m.x, v.x);
        m.y = fmaxf(m.y, v.y);
        m.z = fmaxf(m.z, v.z);
        m.w = fmaxf(m.w, v.w);
        __stcs(q, m);
    }
}

extern "C" void kernel_launch(void* const* d_in, const int* in_sizes, int n_in,
                              void* d_out, int out_size) {
    const float4* in = (const float4*)d_in[0];
    float4* out = (float4*)d_out;
    int threads = 256;
    int blocks = (NCOLS + threads - 1) / threads;  // 512
    revcummax_kernel<<<blocks, threads>>>(in, out);
}

// round 2
// speedup vs baseline: 1.1548x; 1.1548x over previous
#include <cuda_runtime.h>

// Reverse cummax along axis 1 of [B=16, H=128, W=128, C=256] float32.
// out[b,h,w,c] = max over h' >= h of in[b,h',w,c].
//
// Streaming kernel, one thread per (b, w, c4) float4 column walking h from
// the end. Explicit depth-8 prefetch ring buffer guarantees 8 independent
// LDG.128 in flight per thread (R1 showed ptxas collapsed the implicit
// unroll to regs=32 => MLP<=4 => DRAM only 61%).

#define B 16
#define H 128
#define HS 8192               // h-stride in float4 (W*C/4)
#define NCOLS (B * HS)        // 131072 columns
#define D 8                   // pipeline depth
#define NCHUNK (H / D)        // 16

__global__ __launch_bounds__(128) void revcummax_kernel(
    const float4* __restrict__ in, float4* __restrict__ out) {
    int idx = blockIdx.x * blockDim.x + threadIdx.x;

    int b = idx >> 13;           // / HS
    int inner = idx & (HS - 1);
    long long base = (long long)b * H * (long long)HS + inner;

    const float4* pl = in + base + (H - 1) * (long long)HS;   // load cursor
    float4* q = out + base + (H - 1) * (long long)HS;         // store cursor

    // Prologue: fill the ring with h = H-1 .. H-D.
    float4 v[D];
#pragma unroll
    for (int i = 0; i < D; i++) {
        v[i] = __ldcs(pl);
        pl -= HS;
    }

    float4 m;
    m.x = m.y = m.z = m.w = -__int_as_float(0x7f800000);  // -inf

    // Steady state: 15 chunks of 8 with prefetch of the next chunk.
#pragma unroll 1
    for (int c = 0; c < NCHUNK - 1; c++) {
#pragma unroll
        for (int i = 0; i < D; i++) {
            float4 x = v[i];
            v[i] = __ldcs(pl);          // prefetch next chunk, same slot
            pl -= HS;
            m.x = fmaxf(m.x, x.x);
            m.y = fmaxf(m.y, x.y);
            m.z = fmaxf(m.z, x.z);
            m.w = fmaxf(m.w, x.w);
            __stcs(q, m);
            q -= HS;
        }
    }

    // Drain: last chunk (h = D-1 .. 0), no more loads.
#pragma unroll
    for (int i = 0; i < D; i++) {
        float4 x = v[i];
        m.x = fmaxf(m.x, x.x);
        m.y = fmaxf(m.y, x.y);
        m.z = fmaxf(m.z, x.z);
        m.w = fmaxf(m.w, x.w);
        __stcs(q, m);
        q -= HS;
    }
}

extern "C" void kernel_launch(void* const* d_in, const int* in_sizes, int n_in,
                              void* d_out, int out_size) {
    const float4* in = (const float4*)d_in[0];
    float4* out = (float4*)d_out;
    int threads = 128;
    int blocks = NCOLS / threads;  // 1024
    revcummax_kernel<<<blocks, threads>>>(in, out);
}

// round 3
// speedup vs baseline: 1.1776x; 1.0198x over previous
#include <cuda_runtime.h>

// Reverse cummax along axis 1 of [B=16, H=128, W=128, C=256] float32.
// out[b,h,w,c] = max over h' >= h of in[b,h',w,c].
//
// R3: phase-separated memory traffic. Each chunk of 8 h-steps is processed as
// two half-chunks; each half-chunk issues 4 back-to-back LDG.128 (prefetch of
// the NEXT chunk) followed by 4 back-to-back FMAX+STG.128 — longer
// same-direction DRAM bursts, fewer R/W turnarounds. 64-thread blocks give
// finer per-SM load balance (2048 blocks over 148 SMs).

#define B 16
#define H 128
#define HS 8192               // h-stride in float4 (W*C/4)
#define NCOLS (B * HS)        // 131072 columns
#define D 8                   // ring depth (MLP target)
#define HB 4                  // half-batch: loads issued back-to-back
#define NCHUNK (H / D)        // 16

__device__ __forceinline__ float4 fmax4(float4 a, float4 b) {
    float4 r;
    r.x = fmaxf(a.x, b.x);
    r.y = fmaxf(a.y, b.y);
    r.z = fmaxf(a.z, b.z);
    r.w = fmaxf(a.w, b.w);
    return r;
}

__global__ __launch_bounds__(64) void revcummax_kernel(
    const float4* __restrict__ in, float4* __restrict__ out) {
    int idx = blockIdx.x * blockDim.x + threadIdx.x;

    int b = idx >> 13;           // / HS
    int inner = idx & (HS - 1);
    long long base = (long long)b * H * (long long)HS + inner;

    const float4* pl = in + base + (H - 1) * (long long)HS;   // load cursor
    float4* q = out + base + (H - 1) * (long long)HS;         // store cursor

    // Prologue: fill the ring with h = H-1 .. H-D (8 loads back-to-back).
    float4 v[D];
#pragma unroll
    for (int i = 0; i < D; i++) {
        v[i] = __ldcs(pl);
        pl -= HS;
    }

    float4 m;
    m.x = m.y = m.z = m.w = -__int_as_float(0x7f800000);  // -inf

    // Steady state: 15 chunks. Each chunk = 2 half-chunks of
    // [4 loads] then [4 max+stores].
#pragma unroll 1
    for (int c = 0; c < NCHUNK - 1; c++) {
#pragma unroll
        for (int g = 0; g < D / HB; g++) {
            float4 x[HB];
            // Phase 1: grab current values, issue 4 prefetch loads back-to-back.
#pragma unroll
            for (int i = 0; i < HB; i++) {
                x[i] = v[g * HB + i];
                v[g * HB + i] = __ldcs(pl);
                pl -= HS;
            }
            // Phase 2: 4 max+stores back-to-back.
#pragma unroll
            for (int i = 0; i < HB; i++) {
                m = fmax4(m, x[i]);
                __stcs(q, m);
                q -= HS;
            }
        }
    }

    // Drain: last chunk (h = D-1 .. 0), stores only.
#pragma unroll
    for (int i = 0; i < D; i++) {
        m = fmax4(m, v[i]);
        __stcs(q, m);
        q -= HS;
    }
}

extern "C" void kernel_launch(void* const* d_in, const int* in_sizes, int n_in,
                              void* d_out, int out_size) {
    const float4* in = (const float4*)d_in[0];
    float4* out = (float4*)d_out;
    int threads = 64;
    int blocks = NCOLS / threads;  // 2048
    revcummax_kernel<<<blocks, threads>>>(in, out);
}